// round 16
// baseline (speedup 1.0000x reference)
#include <cuda_runtime.h>
#include <cstddef>

#define BATCH   8
#define T_LEN   4096
#define HC      256
#define HD      512
#define NROWS   (BATCH * T_LEN)

__device__ float g_wx[NROWS * HD];   // input-projection output
__device__ float g_h0[NROWS * HD];   // layer-0 hidden states

// ---------------------------------------------------------------- helpers
static __device__ __forceinline__ unsigned su32(const void* p) {
    return (unsigned)__cvta_generic_to_shared(p);
}
static __device__ __forceinline__ unsigned long long packf2(float lo, float hi) {
    unsigned long long r;
    asm("mov.b64 %0, {%1, %2};" : "=l"(r) : "f"(lo), "f"(hi));
    return r;
}
static __device__ __forceinline__ void unpackf2(unsigned long long v, float& lo, float& hi) {
    asm("mov.b64 {%0, %1}, %2;" : "=f"(lo), "=f"(hi) : "l"(v));
}
static __device__ __forceinline__ float hw_tanh(float x) {
    float y;
    asm("tanh.approx.f32 %0, %1;" : "=f"(y) : "f"(x));
    return y;
}
static __device__ __forceinline__ void mbar_wait(unsigned addr, unsigned parity) {
    asm volatile(
        "{\n\t.reg .pred P;\n"
        "LW_%=:\n\t"
        "mbarrier.try_wait.parity.acquire.cluster.shared::cta.b64 P, [%0], %1, 0x989680;\n\t"
        "@P bra LD_%=;\n\t"
        "bra LW_%=;\n"
        "LD_%=:\n\t}"
        :: "r"(addr), "r"(parity) : "memory");
}
static __device__ __forceinline__ void st_async64(unsigned dst, unsigned long long v, unsigned mb) {
    asm volatile("st.async.shared::cluster.mbarrier::complete_tx::bytes.b64 [%0], %1, [%2];"
                 :: "r"(dst), "l"(v), "r"(mb) : "memory");
}

// ---------------------------------------------------------------------------
// Projection GEMM (unchanged): Y[N,512] = X[N,512] @ Mw[512,512] + bias
// ---------------------------------------------------------------------------
__global__ __launch_bounds__(256) void proj_kernel(
    const float* __restrict__ X,
    const float* __restrict__ wr, const float* __restrict__ wi,
    const float* __restrict__ br, const float* __restrict__ bi,
    float* __restrict__ Y)
{
    __shared__ float As[16][132];
    __shared__ float Bs[16][132];

    const int bm  = blockIdx.x * 128;
    const int bn  = blockIdx.y * 128;
    const int tid = threadIdx.x;
    const int tx  = tid & 15;
    const int ty  = tid >> 4;
    const int am  = tid >> 1;
    const int ak  = (tid & 1) * 8;
    const int bk  = tid >> 4;
    const int bj  = (tid & 15) * 8;
    const bool jhi = (bn + bj) >= 256;
    const int  jj  = (bn + bj) & 255;

    float acc[8][8];
#pragma unroll
    for (int r = 0; r < 8; ++r)
#pragma unroll
        for (int c = 0; c < 8; ++c) acc[r][c] = 0.f;

    for (int k0 = 0; k0 < HD; k0 += 16) {
        const float* xrow = X + (size_t)(bm + am) * HD + k0 + ak;
        float4 a0 = *(const float4*)(xrow);
        float4 a1 = *(const float4*)(xrow + 4);
        As[ak + 0][am] = a0.x; As[ak + 1][am] = a0.y;
        As[ak + 2][am] = a0.z; As[ak + 3][am] = a0.w;
        As[ak + 4][am] = a1.x; As[ak + 5][am] = a1.y;
        As[ak + 6][am] = a1.z; As[ak + 7][am] = a1.w;
        {
            int k = k0 + bk;
            float4 b0, b1;
            if (k < 256) {
                const float* src = (jhi ? wi : wr) + (size_t)k * 256 + jj;
                b0 = *(const float4*)(src);
                b1 = *(const float4*)(src + 4);
            } else {
                const float* src = (jhi ? wr : wi) + (size_t)(k - 256) * 256 + jj;
                b0 = *(const float4*)(src);
                b1 = *(const float4*)(src + 4);
                if (!jhi) {
                    b0.x = -b0.x; b0.y = -b0.y; b0.z = -b0.z; b0.w = -b0.w;
                    b1.x = -b1.x; b1.y = -b1.y; b1.z = -b1.z; b1.w = -b1.w;
                }
            }
            *(float4*)&Bs[bk][bj]     = b0;
            *(float4*)&Bs[bk][bj + 4] = b1;
        }
        __syncthreads();
#pragma unroll
        for (int kk = 0; kk < 16; ++kk) {
            float4 av0 = *(const float4*)&As[kk][ty * 8];
            float4 av1 = *(const float4*)&As[kk][ty * 8 + 4];
            float4 bv0 = *(const float4*)&Bs[kk][tx * 8];
            float4 bv1 = *(const float4*)&Bs[kk][tx * 8 + 4];
            float a[8] = {av0.x, av0.y, av0.z, av0.w, av1.x, av1.y, av1.z, av1.w};
            float b[8] = {bv0.x, bv0.y, bv0.z, bv0.w, bv1.x, bv1.y, bv1.z, bv1.w};
#pragma unroll
            for (int r = 0; r < 8; ++r)
#pragma unroll
                for (int c = 0; c < 8; ++c)
                    acc[r][c] = fmaf(a[r], b[c], acc[r][c]);
        }
        __syncthreads();
    }

    const int col0 = bn + tx * 8;
    float bias[8];
#pragma unroll
    for (int c = 0; c < 8; ++c) {
        int j = col0 + c;
        bias[c] = (j < 256) ? br[j] : bi[j - 256];
    }
#pragma unroll
    for (int r = 0; r < 8; ++r) {
        float* yrow = Y + (size_t)(bm + ty * 8 + r) * HD + col0;
        *(float4*)(yrow)     = make_float4(acc[r][0]+bias[0], acc[r][1]+bias[1],
                                           acc[r][2]+bias[2], acc[r][3]+bias[3]);
        *(float4*)(yrow + 4) = make_float4(acc[r][4]+bias[4], acc[r][5]+bias[5],
                                           acc[r][6]+bias[6], acc[r][7]+bias[7]);
    }
}

// ---------------------------------------------------------------------------
// Recurrent scan: 8 clusters x 8 CTAs x 256 threads (R9 compute core).
// Tail change vs R9: after the shfl reduce, ALL lanes hold the sums, so
// lanes 0-7 and 16-23 of EVERY warp compute tanh for their jg and fire two
// st.async.b64 directly from registers to peer d=lane&7 — no staging STS,
// no __syncthreads, no fence, no bulk. Barrier: count=1, expect 2048B/phase
// (8 CTAs x 8 warps x 32B), re-armed by tid0 after its wait (same induction
// as R9: tid0's re-arm precedes warp0's sends in program order, and every
// remote next-phase send is gated through the barrier on those bytes).
// ---------------------------------------------------------------------------
__global__ void __cluster_dims__(8, 1, 1) __launch_bounds__(256, 1)
scan_kernel(const float* __restrict__ wx,
            const float* __restrict__ ur, const float* __restrict__ ui,
            const float* __restrict__ ubr, const float* __restrict__ ubi,
            float* __restrict__ out)
{
    __shared__ float hbuf[2][HD];                       // 2 x 2048 B
    __shared__ __align__(8) unsigned long long mbar[2];

    unsigned rank;
    asm("mov.u32 %0, %%cluster_ctarank;" : "=r"(rank));
    const int b    = blockIdx.x >> 3;
    const int tid  = threadIdx.x;
    const int lane = tid & 31;
    const int jg   = tid >> 4;
    const int kg   = tid & 15;
    const int j0   = (int)rank * 64 + jg * 4;
    const int jj   = j0 & 255;
    const bool jhi = j0 >= 256;

    const unsigned hb_u32 = su32(&hbuf[0][0]);
    const unsigned mb_u32 = su32(&mbar[0]);

    if (tid == 0) {
        asm volatile("mbarrier.init.shared.b64 [%0], %1;" :: "r"(mb_u32),     "r"(1u) : "memory");
        asm volatile("mbarrier.init.shared.b64 [%0], %1;" :: "r"(mb_u32 + 8), "r"(1u) : "memory");
        asm volatile("mbarrier.arrive.expect_tx.shared::cta.b64 _, [%0], %1;"
                     :: "r"(mb_u32),     "r"(2048u) : "memory");
        asm volatile("mbarrier.arrive.expect_tx.shared::cta.b64 _, [%0], %1;"
                     :: "r"(mb_u32 + 8), "r"(2048u) : "memory");
    }
    __syncthreads();
    asm volatile("barrier.cluster.arrive.aligned;" ::: "memory");
    asm volatile("barrier.cluster.wait.aligned;"   ::: "memory");

    // producer mapping: active lanes (lane&15)<8; peer d = lane&7.
    const bool prod = (lane & 15) < 8;
    unsigned dsth_l = 0, dstm_l = 0;
    {
        const int d = lane & 7;
        asm("mapa.shared::cluster.u32 %0, %1, %2;" : "=r"(dsth_l) : "r"(hb_u32), "r"(d));
        asm("mapa.shared::cluster.u32 %0, %1, %2;" : "=r"(dstm_l) : "r"(mb_u32), "r"(d));
    }
    // slice byte offset at the destination: rank*256 + jg*16
    const unsigned dst_off = (unsigned)(rank * 256 + jg * 16);

    // ---- weight slice into registers, packed f32x2 along k ----
    unsigned long long w2[4][16];
#pragma unroll
    for (int q = 0; q < 8; ++q) {
        const int k = q * 64 + kg * 4;
        float4 r0, r1, r2, r3;
        if (k < 256) {
            const float* src = (jhi ? ui : ur) + (size_t)k * 256 + jj;
            r0 = *(const float4*)(src);
            r1 = *(const float4*)(src + 256);
            r2 = *(const float4*)(src + 512);
            r3 = *(const float4*)(src + 768);
        } else {
            const float* src = (jhi ? ur : ui) + (size_t)(k - 256) * 256 + jj;
            const float s = jhi ? 1.f : -1.f;
            r0 = *(const float4*)(src);
            r1 = *(const float4*)(src + 256);
            r2 = *(const float4*)(src + 512);
            r3 = *(const float4*)(src + 768);
            r0.x *= s; r0.y *= s; r0.z *= s; r0.w *= s;
            r1.x *= s; r1.y *= s; r1.z *= s; r1.w *= s;
            r2.x *= s; r2.y *= s; r2.z *= s; r2.w *= s;
            r3.x *= s; r3.y *= s; r3.z *= s; r3.w *= s;
        }
        w2[0][2*q]   = packf2(r0.x, r1.x);
        w2[1][2*q]   = packf2(r0.y, r1.y);
        w2[2][2*q]   = packf2(r0.z, r1.z);
        w2[3][2*q]   = packf2(r0.w, r1.w);
        w2[0][2*q+1] = packf2(r2.x, r3.x);
        w2[1][2*q+1] = packf2(r2.y, r3.y);
        w2[2][2*q+1] = packf2(r2.z, r3.z);
        w2[3][2*q+1] = packf2(r2.w, r3.w);
    }
    const float4 ub = jhi ? *(const float4*)(ubi + jj)
                          : *(const float4*)(ubr + jj);

    const float* wx_b  = wx  + (size_t)b * (T_LEN * HD);
    float*       out_b = out + (size_t)b * (T_LEN * HD);

    const bool is_out_lane = ((lane & 15) == 8);

    // ---- t = 0 (h_prev = 0) ----
    {
        float4 wv = *(const float4*)(wx_b + j0);
        wv.x += ub.x; wv.y += ub.y; wv.z += ub.z; wv.w += ub.w;
        if (prod | is_out_lane) {
            float4 yv;
            yv.x = hw_tanh(wv.x);
            yv.y = hw_tanh(wv.y);
            yv.z = hw_tanh(wv.z);
            yv.w = hw_tanh(wv.w);
            if (prod) {
                unsigned a = dsth_l + dst_off;   // buf 0
                st_async64(a,     packf2(yv.x, yv.y), dstm_l);
                st_async64(a + 8, packf2(yv.z, yv.w), dstm_l);
            } else {
                *(float4*)(out_b + j0) = yv;
            }
        }
    }

    for (int t = 1; t < T_LEN; ++t) {
        float4 wv = *(const float4*)(wx_b + (size_t)t * HD + j0);
        wv.x += ub.x; wv.y += ub.y; wv.z += ub.z; wv.w += ub.w;

        const int use  = t - 1;
        const int rbuf = use & 1;
        mbar_wait(mb_u32 + rbuf * 8, (unsigned)((use >> 1) & 1));

        // re-arm this buffer's next phase (precedes warp 0's own sends)
        if (tid == 0) {
            asm volatile("mbarrier.arrive.expect_tx.shared::cta.b64 _, [%0], %1;"
                         :: "r"(mb_u32 + rbuf * 8), "r"(2048u) : "memory");
        }

        unsigned long long h2[16];
        const float* hp = &hbuf[rbuf][0];
#pragma unroll
        for (int q = 0; q < 8; ++q) {
            ulonglong2 v = *(const ulonglong2*)(hp + q * 64 + kg * 4);
            h2[2*q]   = v.x;
            h2[2*q+1] = v.y;
        }

        unsigned long long acc0 = 0, acc1 = 0, acc2 = 0, acc3 = 0;
#pragma unroll
        for (int q = 0; q < 16; ++q) {
            asm("fma.rn.f32x2 %0, %1, %2, %0;" : "+l"(acc0) : "l"(h2[q]), "l"(w2[0][q]));
            asm("fma.rn.f32x2 %0, %1, %2, %0;" : "+l"(acc1) : "l"(h2[q]), "l"(w2[1][q]));
            asm("fma.rn.f32x2 %0, %1, %2, %0;" : "+l"(acc2) : "l"(h2[q]), "l"(w2[2][q]));
            asm("fma.rn.f32x2 %0, %1, %2, %0;" : "+l"(acc3) : "l"(h2[q]), "l"(w2[3][q]));
        }
        float a0, a1, a2, a3, hq;
        unpackf2(acc0, a0, hq); a0 += hq;
        unpackf2(acc1, a1, hq); a1 += hq;
        unpackf2(acc2, a2, hq); a2 += hq;
        unpackf2(acc3, a3, hq); a3 += hq;
#pragma unroll
        for (int off = 1; off < 16; off <<= 1) {
            a0 += __shfl_xor_sync(0xffffffffu, a0, off);
            a1 += __shfl_xor_sync(0xffffffffu, a1, off);
            a2 += __shfl_xor_sync(0xffffffffu, a2, off);
            a3 += __shfl_xor_sync(0xffffffffu, a3, off);
        }

        if (prod | is_out_lane) {
            float4 yv;
            yv.x = hw_tanh(wv.x + a0);
            yv.y = hw_tanh(wv.y + a1);
            yv.z = hw_tanh(wv.z + a2);
            yv.w = hw_tanh(wv.w + a3);
            if (prod) {
                if (t < T_LEN - 1) {
                    const unsigned a = dsth_l + (unsigned)((t & 1) * 2048) + dst_off;
                    const unsigned m = dstm_l + (unsigned)((t & 1) * 8);
                    st_async64(a,     packf2(yv.x, yv.y), m);
                    st_async64(a + 8, packf2(yv.z, yv.w), m);
                }
            } else {
                *(float4*)(out_b + (size_t)t * HD + j0) = yv;
            }
        }
    }

    asm volatile("barrier.cluster.arrive.aligned;" ::: "memory");
    asm volatile("barrier.cluster.wait.aligned;"   ::: "memory");
}

// ---------------------------------------------------------------------------
extern "C" void kernel_launch(void* const* d_in, const int* in_sizes, int n_in,
                              void* d_out, int out_size)
{
    const float* x      = (const float*)d_in[0];
    const float* l0_wr  = (const float*)d_in[1];
    const float* l0_wi  = (const float*)d_in[2];
    const float* l0_wbr = (const float*)d_in[3];
    const float* l0_wbi = (const float*)d_in[4];
    const float* l0_ur  = (const float*)d_in[5];
    const float* l0_ui  = (const float*)d_in[6];
    const float* l0_ubr = (const float*)d_in[7];
    const float* l0_ubi = (const float*)d_in[8];
    const float* l1_wr  = (const float*)d_in[9];
    const float* l1_wi  = (const float*)d_in[10];
    const float* l1_wbr = (const float*)d_in[11];
    const float* l1_wbi = (const float*)d_in[12];
    const float* l1_ur  = (const float*)d_in[13];
    const float* l1_ui  = (const float*)d_in[14];
    const float* l1_ubr = (const float*)d_in[15];
    const float* l1_ubi = (const float*)d_in[16];

    float* out = (float*)d_out;

    void *p_wx_v = nullptr, *p_h0_v = nullptr;
    cudaGetSymbolAddress(&p_wx_v, g_wx);
    cudaGetSymbolAddress(&p_h0_v, g_h0);
    float* p_wx = (float*)p_wx_v;
    float* p_h0 = (float*)p_h0_v;

    dim3 pgrid(NROWS / 128, HD / 128);

    proj_kernel<<<pgrid, 256>>>(x, l0_wr, l0_wi, l0_wbr, l0_wbi, p_wx);
    scan_kernel<<<64, 256>>>(p_wx, l0_ur, l0_ui, l0_ubr, l0_ubi, p_h0);
    proj_kernel<<<pgrid, 256>>>(p_h0, l1_wr, l1_wi, l1_wbr, l1_wbi, p_wx);
    scan_kernel<<<64, 256>>>(p_wx, l1_ur, l1_ui, l1_ubr, l1_ubi, out);
}

// round 17
// speedup vs baseline: 1.4384x; 1.4384x over previous
#include <cuda_runtime.h>
#include <cstddef>

#define BATCH   8
#define T_LEN   4096
#define HC      256
#define HD      512
#define NROWS   (BATCH * T_LEN)

__device__ float g_wx[NROWS * HD];   // input-projection output
__device__ float g_h0[NROWS * HD];   // layer-0 hidden states

// ---------------------------------------------------------------- helpers
static __device__ __forceinline__ unsigned su32(const void* p) {
    return (unsigned)__cvta_generic_to_shared(p);
}
static __device__ __forceinline__ unsigned long long packf2(float lo, float hi) {
    unsigned long long r;
    asm("mov.b64 %0, {%1, %2};" : "=l"(r) : "f"(lo), "f"(hi));
    return r;
}
static __device__ __forceinline__ void unpackf2(unsigned long long v, float& lo, float& hi) {
    asm("mov.b64 {%0, %1}, %2;" : "=f"(lo), "=f"(hi) : "l"(v));
}
static __device__ __forceinline__ float hw_tanh(float x) {
    float y;
    asm("tanh.approx.f32 %0, %1;" : "=f"(y) : "f"(x));
    return y;
}
static __device__ __forceinline__ void mbar_wait(unsigned addr, unsigned parity) {
    asm volatile(
        "{\n\t.reg .pred P;\n"
        "LW_%=:\n\t"
        "mbarrier.try_wait.parity.acquire.cluster.shared::cta.b64 P, [%0], %1, 0x989680;\n\t"
        "@P bra LD_%=;\n\t"
        "bra LW_%=;\n"
        "LD_%=:\n\t}"
        :: "r"(addr), "r"(parity) : "memory");
}
#define FMA2(a, x, y) asm("fma.rn.f32x2 %0, %1, %2, %0;" : "+l"(a) : "l"(x), "l"(y))

// ---------------------------------------------------------------------------
// Projection GEMM: Y[N,512] = X[N,512] @ Mw[512,512] + bias.
// Inner loop vectorized with fma.rn.f32x2: B columns packed in pairs,
// A duplicated into both halves (same fp32 rounding, half the FMA issues).
// ---------------------------------------------------------------------------
__global__ __launch_bounds__(256) void proj_kernel(
    const float* __restrict__ X,
    const float* __restrict__ wr, const float* __restrict__ wi,
    const float* __restrict__ br, const float* __restrict__ bi,
    float* __restrict__ Y)
{
    __shared__ float As[16][132];
    __shared__ float Bs[16][132];

    const int bm  = blockIdx.x * 128;
    const int bn  = blockIdx.y * 128;
    const int tid = threadIdx.x;
    const int tx  = tid & 15;
    const int ty  = tid >> 4;
    const int am  = tid >> 1;
    const int ak  = (tid & 1) * 8;
    const int bk  = tid >> 4;
    const int bj  = (tid & 15) * 8;
    const bool jhi = (bn + bj) >= 256;
    const int  jj  = (bn + bj) & 255;

    unsigned long long acc2[8][4];
#pragma unroll
    for (int r = 0; r < 8; ++r)
#pragma unroll
        for (int c = 0; c < 4; ++c) acc2[r][c] = 0ull;

    for (int k0 = 0; k0 < HD; k0 += 16) {
        const float* xrow = X + (size_t)(bm + am) * HD + k0 + ak;
        float4 a0 = *(const float4*)(xrow);
        float4 a1 = *(const float4*)(xrow + 4);
        As[ak + 0][am] = a0.x; As[ak + 1][am] = a0.y;
        As[ak + 2][am] = a0.z; As[ak + 3][am] = a0.w;
        As[ak + 4][am] = a1.x; As[ak + 5][am] = a1.y;
        As[ak + 6][am] = a1.z; As[ak + 7][am] = a1.w;
        {
            int k = k0 + bk;
            float4 b0, b1;
            if (k < 256) {
                const float* src = (jhi ? wi : wr) + (size_t)k * 256 + jj;
                b0 = *(const float4*)(src);
                b1 = *(const float4*)(src + 4);
            } else {
                const float* src = (jhi ? wr : wi) + (size_t)(k - 256) * 256 + jj;
                b0 = *(const float4*)(src);
                b1 = *(const float4*)(src + 4);
                if (!jhi) {
                    b0.x = -b0.x; b0.y = -b0.y; b0.z = -b0.z; b0.w = -b0.w;
                    b1.x = -b1.x; b1.y = -b1.y; b1.z = -b1.z; b1.w = -b1.w;
                }
            }
            *(float4*)&Bs[bk][bj]     = b0;
            *(float4*)&Bs[bk][bj + 4] = b1;
        }
        __syncthreads();

#pragma unroll
        for (int kk = 0; kk < 16; ++kk) {
            float4 av0 = *(const float4*)&As[kk][ty * 8];
            float4 av1 = *(const float4*)&As[kk][ty * 8 + 4];
            ulonglong2 bv0 = *(const ulonglong2*)&Bs[kk][tx * 8];
            ulonglong2 bv1 = *(const ulonglong2*)&Bs[kk][tx * 8 + 4];
            unsigned long long bp[4] = {bv0.x, bv0.y, bv1.x, bv1.y};
            float a[8] = {av0.x, av0.y, av0.z, av0.w, av1.x, av1.y, av1.z, av1.w};
#pragma unroll
            for (int r = 0; r < 8; ++r) {
                unsigned long long ad = packf2(a[r], a[r]);
#pragma unroll
                for (int c = 0; c < 4; ++c)
                    FMA2(acc2[r][c], ad, bp[c]);
            }
        }
        __syncthreads();
    }

    const int col0 = bn + tx * 8;
    float bias[8];
#pragma unroll
    for (int c = 0; c < 8; ++c) {
        int j = col0 + c;
        bias[c] = (j < 256) ? br[j] : bi[j - 256];
    }
#pragma unroll
    for (int r = 0; r < 8; ++r) {
        float acc[8];
#pragma unroll
        for (int c = 0; c < 4; ++c)
            unpackf2(acc2[r][c], acc[2 * c], acc[2 * c + 1]);
        float* yrow = Y + (size_t)(bm + ty * 8 + r) * HD + col0;
        *(float4*)(yrow)     = make_float4(acc[0]+bias[0], acc[1]+bias[1],
                                           acc[2]+bias[2], acc[3]+bias[3]);
        *(float4*)(yrow + 4) = make_float4(acc[4]+bias[4], acc[5]+bias[5],
                                           acc[6]+bias[6], acc[7]+bias[7]);
    }
}

// ---------------------------------------------------------------------------
// Recurrent scan: exact R9 (best known: 3.08us/launch).
// ---------------------------------------------------------------------------
__global__ void __cluster_dims__(8, 1, 1) __launch_bounds__(256, 1)
scan_kernel(const float* __restrict__ wx,
            const float* __restrict__ ur, const float* __restrict__ ui,
            const float* __restrict__ ubr, const float* __restrict__ ubi,
            float* __restrict__ out)
{
    __shared__ float hbuf[2][HD];
    __shared__ __align__(16) float stage[64];
    __shared__ __align__(8) unsigned long long mbar[2];

    unsigned rank;
    asm("mov.u32 %0, %%cluster_ctarank;" : "=r"(rank));
    const int b    = blockIdx.x >> 3;
    const int tid  = threadIdx.x;
    const int lane = tid & 31;
    const int jg   = tid >> 4;
    const int kg   = tid & 15;
    const int j0   = (int)rank * 64 + jg * 4;
    const int jj   = j0 & 255;
    const bool jhi = j0 >= 256;

    const unsigned hb_u32 = su32(&hbuf[0][0]);
    const unsigned st_u32 = su32(&stage[0]);
    const unsigned mb_u32 = su32(&mbar[0]);

    if (tid == 0) {
        asm volatile("mbarrier.init.shared.b64 [%0], %1;" :: "r"(mb_u32),     "r"(1u) : "memory");
        asm volatile("mbarrier.init.shared.b64 [%0], %1;" :: "r"(mb_u32 + 8), "r"(1u) : "memory");
        asm volatile("mbarrier.arrive.expect_tx.shared::cta.b64 _, [%0], %1;"
                     :: "r"(mb_u32),     "r"(2048u) : "memory");
        asm volatile("mbarrier.arrive.expect_tx.shared::cta.b64 _, [%0], %1;"
                     :: "r"(mb_u32 + 8), "r"(2048u) : "memory");
    }
    __syncthreads();
    asm volatile("barrier.cluster.arrive.aligned;" ::: "memory");
    asm volatile("barrier.cluster.wait.aligned;"   ::: "memory");

    unsigned dsth_l, dstm_l;
    {
        const int d = tid & 7;
        asm("mapa.shared::cluster.u32 %0, %1, %2;" : "=r"(dsth_l) : "r"(hb_u32), "r"(d));
        asm("mapa.shared::cluster.u32 %0, %1, %2;" : "=r"(dstm_l) : "r"(mb_u32), "r"(d));
    }
    const unsigned dst_slot = dsth_l + (unsigned)(rank * 256);

    unsigned long long w2[4][16];
#pragma unroll
    for (int q = 0; q < 8; ++q) {
        const int k = q * 64 + kg * 4;
        float4 r0, r1, r2, r3;
        if (k < 256) {
            const float* src = (jhi ? ui : ur) + (size_t)k * 256 + jj;
            r0 = *(const float4*)(src);
            r1 = *(const float4*)(src + 256);
            r2 = *(const float4*)(src + 512);
            r3 = *(const float4*)(src + 768);
        } else {
            const float* src = (jhi ? ur : ui) + (size_t)(k - 256) * 256 + jj;
            const float s = jhi ? 1.f : -1.f;
            r0 = *(const float4*)(src);
            r1 = *(const float4*)(src + 256);
            r2 = *(const float4*)(src + 512);
            r3 = *(const float4*)(src + 768);
            r0.x *= s; r0.y *= s; r0.z *= s; r0.w *= s;
            r1.x *= s; r1.y *= s; r1.z *= s; r1.w *= s;
            r2.x *= s; r2.y *= s; r2.z *= s; r2.w *= s;
            r3.x *= s; r3.y *= s; r3.z *= s; r3.w *= s;
        }
        w2[0][2*q]   = packf2(r0.x, r1.x);
        w2[1][2*q]   = packf2(r0.y, r1.y);
        w2[2][2*q]   = packf2(r0.z, r1.z);
        w2[3][2*q]   = packf2(r0.w, r1.w);
        w2[0][2*q+1] = packf2(r2.x, r3.x);
        w2[1][2*q+1] = packf2(r2.y, r3.y);
        w2[2][2*q+1] = packf2(r2.z, r3.z);
        w2[3][2*q+1] = packf2(r2.w, r3.w);
    }
    const float4 ub = jhi ? *(const float4*)(ubi + jj)
                          : *(const float4*)(ubr + jj);

    const float* wx_b  = wx  + (size_t)b * (T_LEN * HD);
    float*       out_b = out + (size_t)b * (T_LEN * HD);

    const bool is_stage_lane = ((lane & 15) == 0);
    const bool is_out_lane   = ((lane & 15) == 8);

    // ---- t = 0 (h_prev = 0) ----
    {
        float4 wv = *(const float4*)(wx_b + j0);
        wv.x += ub.x; wv.y += ub.y; wv.z += ub.z; wv.w += ub.w;
        if (is_stage_lane | is_out_lane) {
            float4 yv;
            yv.x = hw_tanh(wv.x);
            yv.y = hw_tanh(wv.y);
            yv.z = hw_tanh(wv.z);
            yv.w = hw_tanh(wv.w);
            if (is_stage_lane) *(float4*)&stage[jg * 4] = yv;
            else               *(float4*)(out_b + j0) = yv;
        }
        __syncthreads();
        if (tid < 8) {
            asm volatile("fence.proxy.async.shared::cta;" ::: "memory");
            asm volatile(
                "cp.async.bulk.shared::cluster.shared::cta.mbarrier::complete_tx::bytes "
                "[%0], [%1], %2, [%3];"
                :: "r"(dst_slot), "r"(st_u32), "r"(256u), "r"(dstm_l)
                : "memory");
        }
    }

    for (int t = 1; t < T_LEN; ++t) {
        float4 wv = *(const float4*)(wx_b + (size_t)t * HD + j0);
        wv.x += ub.x; wv.y += ub.y; wv.z += ub.z; wv.w += ub.w;

        const int use  = t - 1;
        const int rbuf = use & 1;
        mbar_wait(mb_u32 + rbuf * 8, (unsigned)((use >> 1) & 1));

        if (tid == 0) {
            asm volatile("mbarrier.arrive.expect_tx.shared::cta.b64 _, [%0], %1;"
                         :: "r"(mb_u32 + rbuf * 8), "r"(2048u) : "memory");
        }

        unsigned long long h2[16];
        const float* hp = &hbuf[rbuf][0];
#pragma unroll
        for (int q = 0; q < 8; ++q) {
            ulonglong2 v = *(const ulonglong2*)(hp + q * 64 + kg * 4);
            h2[2*q]   = v.x;
            h2[2*q+1] = v.y;
        }

        unsigned long long acc0 = 0, acc1 = 0, acc2 = 0, acc3 = 0;
#pragma unroll
        for (int q = 0; q < 16; ++q) {
            FMA2(acc0, h2[q], w2[0][q]);
            FMA2(acc1, h2[q], w2[1][q]);
            FMA2(acc2, h2[q], w2[2][q]);
            FMA2(acc3, h2[q], w2[3][q]);
        }
        float a0, a1, a2, a3, hq;
        unpackf2(acc0, a0, hq); a0 += hq;
        unpackf2(acc1, a1, hq); a1 += hq;
        unpackf2(acc2, a2, hq); a2 += hq;
        unpackf2(acc3, a3, hq); a3 += hq;
#pragma unroll
        for (int off = 1; off < 16; off <<= 1) {
            a0 += __shfl_xor_sync(0xffffffffu, a0, off);
            a1 += __shfl_xor_sync(0xffffffffu, a1, off);
            a2 += __shfl_xor_sync(0xffffffffu, a2, off);
            a3 += __shfl_xor_sync(0xffffffffu, a3, off);
        }

        if (is_stage_lane | is_out_lane) {
            float4 yv;
            yv.x = hw_tanh(wv.x + a0);
            yv.y = hw_tanh(wv.y + a1);
            yv.z = hw_tanh(wv.z + a2);
            yv.w = hw_tanh(wv.w + a3);
            if (is_stage_lane) {
                if (t < T_LEN - 1) *(float4*)&stage[jg * 4] = yv;
            } else {
                *(float4*)(out_b + (size_t)t * HD + j0) = yv;
            }
        }

        if (t < T_LEN - 1) {
            __syncthreads();
            if (tid < 8) {
                const unsigned boff = (unsigned)((t & 1) * 2048);
                const unsigned moff = (unsigned)((t & 1) * 8);
                asm volatile("fence.proxy.async.shared::cta;" ::: "memory");
                asm volatile(
                    "cp.async.bulk.shared::cluster.shared::cta.mbarrier::complete_tx::bytes "
                    "[%0], [%1], %2, [%3];"
                    :: "r"(dst_slot + boff), "r"(st_u32), "r"(256u), "r"(dstm_l + moff)
                    : "memory");
            }
        }
    }

    asm volatile("barrier.cluster.arrive.aligned;" ::: "memory");
    asm volatile("barrier.cluster.wait.aligned;"   ::: "memory");
}

// ---------------------------------------------------------------------------
extern "C" void kernel_launch(void* const* d_in, const int* in_sizes, int n_in,
                              void* d_out, int out_size)
{
    const float* x      = (const float*)d_in[0];
    const float* l0_wr  = (const float*)d_in[1];
    const float* l0_wi  = (const float*)d_in[2];
    const float* l0_wbr = (const float*)d_in[3];
    const float* l0_wbi = (const float*)d_in[4];
    const float* l0_ur  = (const float*)d_in[5];
    const float* l0_ui  = (const float*)d_in[6];
    const float* l0_ubr = (const float*)d_in[7];
    const float* l0_ubi = (const float*)d_in[8];
    const float* l1_wr  = (const float*)d_in[9];
    const float* l1_wi  = (const float*)d_in[10];
    const float* l1_wbr = (const float*)d_in[11];
    const float* l1_wbi = (const float*)d_in[12];
    const float* l1_ur  = (const float*)d_in[13];
    const float* l1_ui  = (const float*)d_in[14];
    const float* l1_ubr = (const float*)d_in[15];
    const float* l1_ubi = (const float*)d_in[16];

    float* out = (float*)d_out;

    void *p_wx_v = nullptr, *p_h0_v = nullptr;
    cudaGetSymbolAddress(&p_wx_v, g_wx);
    cudaGetSymbolAddress(&p_h0_v, g_h0);
    float* p_wx = (float*)p_wx_v;
    float* p_h0 = (float*)p_h0_v;

    dim3 pgrid(NROWS / 128, HD / 128);

    proj_kernel<<<pgrid, 256>>>(x, l0_wr, l0_wi, l0_wbr, l0_wbi, p_wx);
    scan_kernel<<<64, 256>>>(p_wx, l0_ur, l0_ui, l0_ubr, l0_ubi, p_h0);
    proj_kernel<<<pgrid, 256>>>(p_h0, l1_wr, l1_wi, l1_wbr, l1_wbi, p_wx);
    scan_kernel<<<64, 256>>>(p_wx, l1_ur, l1_ui, l1_ubr, l1_ubi, out);
}